// round 3
// baseline (speedup 1.0000x reference)
#include <cuda_runtime.h>

#define B_      2
#define CIN     64
#define HIN     128
#define WIN     256
#define COUT    64
#define KK      9
#define HOUT    128
#define WOUT    256
#define HW      (HIN * WIN)     // 32768
#define HWO     (HOUT * WOUT)   // 32768
#define TILE_P  64
#define NTHREADS 128

// Pre-transposed weights: wT[k][c][o]  (scratch; no allocation allowed)
__device__ float g_wT[KK * CIN * COUT];

__global__ void transpose_weight_kernel(const float* __restrict__ w) {
    int idx = blockIdx.x * blockDim.x + threadIdx.x;
    if (idx < COUT * CIN * KK) {
        int k = idx % KK;
        int c = (idx / KK) % CIN;
        int o = idx / (KK * CIN);
        g_wT[(k * CIN + c) * COUT + o] = w[idx];
    }
}

// ---- packed fp32x2 helpers ----
__device__ __forceinline__ void fma2(unsigned long long& d,
                                     unsigned long long a,
                                     unsigned long long b) {
    asm("fma.rn.f32x2 %0, %1, %2, %0;" : "+l"(d) : "l"(a), "l"(b));
}
__device__ __forceinline__ void unpack2(unsigned long long v, float& a, float& b) {
    asm("mov.b64 {%0, %1}, %2;" : "=f"(a), "=f"(b) : "l"(v));
}

__global__ __launch_bounds__(NTHREADS) void deform_conv_kernel(
    const float* __restrict__ x,
    const float* __restrict__ offset,
    const float* __restrict__ bias,
    float* __restrict__ out)
{
    // samples stored DUPLICATED: s_smp2[c][pix] = (v, v)  -> 32 KB
    __shared__ __align__(16) float2 s_smp2[CIN][TILE_P];
    __shared__ __align__(16) float  s_wk[CIN][COUT];       // 16 KB  (total 48 KB)

    const int tid    = threadIdx.x;
    const int wtile  = blockIdx.x;   // 0..3
    const int h      = blockIdx.y;   // 0..127
    const int b      = blockIdx.z;   // 0..1
    const int w_base = wtile * TILE_P;

    // ---- sampling role: warp pairs cover (pixel, channel-half) ----
    const int warp   = tid >> 5;
    const int lane   = tid & 31;
    const int sp_pix = ((warp & 1) << 5) | lane;   // 0..63
    const int sp_c0  = (warp >> 1) << 5;           // 0 or 32
    const int w_out  = w_base + sp_pix;
    const float* xb  = x + (size_t)b * CIN * HW;

    // ---- FMA role: 8 output-channels x 4 pixels per thread ----
    const int og = tid & 7;    // outputs [og*8, og*8+8)
    const int pg = tid >> 3;   // pixels  [pg*4, pg*4+4)

    // acc2[j][p] holds outputs (og*8+2j, og*8+2j+1) at pixel pg*4+p
    unsigned long long acc2[4][4];
#pragma unroll
    for (int j = 0; j < 4; j++)
#pragma unroll
        for (int p = 0; p < 4; p++) acc2[j][p] = 0ULL;

    for (int k = 0; k < KK; k++) {
        __syncthreads();   // protect s_smp2 / s_wk from previous iteration's readers

        // stage weights for this k: wT[k][c][o] -> s_wk[c][o] (float4, coalesced)
        {
            const float4* wk_src = reinterpret_cast<const float4*>(g_wT + k * CIN * COUT);
            float4* dst = reinterpret_cast<float4*>(&s_wk[0][0]);
#pragma unroll
            for (int i = 0; i < (CIN * COUT / 4) / NTHREADS; i++)
                dst[i * NTHREADS + tid] = wk_src[i * NTHREADS + tid];
        }

        // deformable bilinear sampling -> s_smp2[c][pix] = (v,v)
        {
            const int ki = k / 3, kj = k % 3;
            const float offy = offset[(((size_t)b * KK + k) * 2 + 0) * HWO + h * WOUT + w_out];
            const float offx = offset[(((size_t)b * KK + k) * 2 + 1) * HWO + h * WOUT + w_out];
            const float py = (float)(h - 1 + ki) + offy;
            const float px = (float)(w_out - 1 + kj) + offx;
            const float y0f = floorf(py), x0f = floorf(px);
            const float wy = py - y0f, wx = px - x0f;
            const int y0 = (int)y0f, x0 = (int)x0f;
            const int y1 = y0 + 1, x1 = x0 + 1;
            const bool vy0 = (y0 >= 0) & (y0 < HIN);
            const bool vy1 = (y1 >= 0) & (y1 < HIN);
            const bool vx0 = (x0 >= 0) & (x0 < WIN);
            const bool vx1 = (x1 >= 0) & (x1 < WIN);

            float w00 = (1.f - wy) * (1.f - wx);
            float w01 = (1.f - wy) * wx;
            float w10 = wy * (1.f - wx);
            float w11 = wy * wx;
            if (!(vy0 && vx0)) w00 = 0.f;
            if (!(vy0 && vx1)) w01 = 0.f;
            if (!(vy1 && vx0)) w10 = 0.f;
            if (!(vy1 && vx1)) w11 = 0.f;
            const int i00 = (vy0 && vx0) ? (y0 * WIN + x0) : 0;
            const int i01 = (vy0 && vx1) ? (y0 * WIN + x1) : 0;
            const int i10 = (vy1 && vx0) ? (y1 * WIN + x0) : 0;
            const int i11 = (vy1 && vx1) ? (y1 * WIN + x1) : 0;

            const float* p = xb + (size_t)sp_c0 * HW;
#pragma unroll 4
            for (int c = 0; c < 32; c++) {
                float v = w00 * __ldg(p + i00) + w01 * __ldg(p + i01)
                        + w10 * __ldg(p + i10) + w11 * __ldg(p + i11);
                s_smp2[sp_c0 + c][sp_pix] = make_float2(v, v);
                p += HW;
            }
        }

        __syncthreads();

        // GEMM phase (packed f32x2): acc[o][p] += W[k][c][o] * s[c][p]
        // sample-pairs come straight out of smem as b64 halves of LDS.128
#pragma unroll 4
        for (int c = 0; c < CIN; c++) {
            const ulonglong2 sp01 = *reinterpret_cast<const ulonglong2*>(&s_smp2[c][pg << 2]);       // (s0,s0),(s1,s1)
            const ulonglong2 sp23 = *reinterpret_cast<const ulonglong2*>(&s_smp2[c][(pg << 2) + 2]); // (s2,s2),(s3,s3)
            const ulonglong2 wp01 = *reinterpret_cast<const ulonglong2*>(&s_wk[c][og << 3]);         // (w0,w1),(w2,w3)
            const ulonglong2 wp23 = *reinterpret_cast<const ulonglong2*>(&s_wk[c][(og << 3) + 4]);   // (w4,w5),(w6,w7)

            fma2(acc2[0][0], wp01.x, sp01.x); fma2(acc2[0][1], wp01.x, sp01.y);
            fma2(acc2[0][2], wp01.x, sp23.x); fma2(acc2[0][3], wp01.x, sp23.y);
            fma2(acc2[1][0], wp01.y, sp01.x); fma2(acc2[1][1], wp01.y, sp01.y);
            fma2(acc2[1][2], wp01.y, sp23.x); fma2(acc2[1][3], wp01.y, sp23.y);
            fma2(acc2[2][0], wp23.x, sp01.x); fma2(acc2[2][1], wp23.x, sp01.y);
            fma2(acc2[2][2], wp23.x, sp23.x); fma2(acc2[2][3], wp23.x, sp23.y);
            fma2(acc2[3][0], wp23.y, sp01.x); fma2(acc2[3][1], wp23.y, sp01.y);
            fma2(acc2[3][2], wp23.y, sp23.x); fma2(acc2[3][3], wp23.y, sp23.y);
        }
    }

    // epilogue: unpack, add bias, float4 stores
    float vals[8][4];
#pragma unroll
    for (int j = 0; j < 4; j++)
#pragma unroll
        for (int p = 0; p < 4; p++)
            unpack2(acc2[j][p], vals[2 * j][p], vals[2 * j + 1][p]);

#pragma unroll
    for (int i = 0; i < 8; i++) {
        const int o = (og << 3) + i;
        const float bv = __ldg(bias + o);
        float4 r = make_float4(vals[i][0] + bv, vals[i][1] + bv,
                               vals[i][2] + bv, vals[i][3] + bv);
        *reinterpret_cast<float4*>(
            out + (((size_t)b * COUT + o) * HOUT + h) * WOUT + w_base + (pg << 2)) = r;
    }
}

extern "C" void kernel_launch(void* const* d_in, const int* in_sizes, int n_in,
                              void* d_out, int out_size)
{
    const float* x      = (const float*)d_in[0];
    const float* offset = (const float*)d_in[1];
    const float* weight = (const float*)d_in[2];
    const float* bias   = (const float*)d_in[3];
    float* out          = (float*)d_out;

    transpose_weight_kernel<<<(COUT * CIN * KK + 255) / 256, 256>>>(weight);

    dim3 grid(WOUT / TILE_P, HOUT, B_);
    deform_conv_kernel<<<grid, NTHREADS>>>(x, offset, bias, out);
}